// round 1
// baseline (speedup 1.0000x reference)
#include <cuda_runtime.h>

#define NN 50000
#define NE 800000
#define KF 128

// ---------------- device scratch (no allocs allowed) ----------------
__device__ __align__(16) float g_h[NN * 128];
__device__ __align__(16) float g_x[NN * 128];
__device__ int   g_deg[NN];
__device__ float g_invdeg[NN];
__device__ int   g_rowptr[NN + 1];
__device__ int   g_cursor[NN];
__device__ int   g_esrc[NE];

// ---------------- CSR build ----------------
__global__ void zero_deg_kernel() {
    int v = blockIdx.x * blockDim.x + threadIdx.x;
    if (v < NN) g_deg[v] = 0;
}

__global__ void hist_kernel(const int* __restrict__ dst) {
    int e = blockIdx.x * blockDim.x + threadIdx.x;
    if (e < NE) atomicAdd(&g_deg[dst[e]], 1);
}

// single-block exclusive scan over degrees; also writes invdeg + zeroes cursor
__global__ void scan_kernel() {
    __shared__ int partial[1024];
    int t = threadIdx.x;
    const int C = (NN + 1023) / 1024;  // 49
    int beg = t * C;
    int end = min(beg + C, NN);
    int s = 0;
    for (int v = beg; v < end; ++v) s += g_deg[v];
    partial[t] = s;
    __syncthreads();
    for (int off = 1; off < 1024; off <<= 1) {
        int val = (t >= off) ? partial[t - off] : 0;
        __syncthreads();
        partial[t] += val;
        __syncthreads();
    }
    int run = (t == 0) ? 0 : partial[t - 1];
    for (int v = beg; v < end; ++v) {
        int d = g_deg[v];
        g_rowptr[v] = run;
        g_cursor[v] = 0;
        g_invdeg[v] = 1.0f / (float)(d > 0 ? d : 1);
        run += d;
    }
    if (t == 1023) g_rowptr[NN] = run;
}

__global__ void fill_kernel(const int* __restrict__ src, const int* __restrict__ dst) {
    int e = blockIdx.x * blockDim.x + threadIdx.x;
    if (e < NE) {
        int d = dst[e];
        int p = atomicAdd(&g_cursor[d], 1);
        g_esrc[g_rowptr[d] + p] = src[e];
    }
}

// ---------------- aggregation: warp-per-node gather ----------------
// x[v] = (1+eps[li]) * h[v] + mean_{s in N_in(v)} h[s]
__global__ void aggregate_kernel(const float* __restrict__ h, float* __restrict__ x,
                                 const float* __restrict__ eps, int li) {
    int warp = (blockIdx.x * blockDim.x + threadIdx.x) >> 5;
    if (warp >= NN) return;
    int lane = threadIdx.x & 31;
    int v = warp;
    int beg = g_rowptr[v], end = g_rowptr[v + 1];
    float4 acc = make_float4(0.f, 0.f, 0.f, 0.f);
    int e = beg;
    int col = lane * 4;
    for (; e + 4 <= end; e += 4) {
        int s0 = g_esrc[e + 0];
        int s1 = g_esrc[e + 1];
        int s2 = g_esrc[e + 2];
        int s3 = g_esrc[e + 3];
        float4 a = *(const float4*)(h + (size_t)s0 * 128 + col);
        float4 b = *(const float4*)(h + (size_t)s1 * 128 + col);
        float4 c = *(const float4*)(h + (size_t)s2 * 128 + col);
        float4 d = *(const float4*)(h + (size_t)s3 * 128 + col);
        acc.x += (a.x + b.x) + (c.x + d.x);
        acc.y += (a.y + b.y) + (c.y + d.y);
        acc.z += (a.z + b.z) + (c.z + d.z);
        acc.w += (a.w + b.w) + (c.w + d.w);
    }
    for (; e < end; ++e) {
        int s = g_esrc[e];
        float4 a = *(const float4*)(h + (size_t)s * 128 + col);
        acc.x += a.x; acc.y += a.y; acc.z += a.z; acc.w += a.w;
    }
    float inv = g_invdeg[v];
    float sc = 1.0f + eps[li];
    float4 hv = *(const float4*)(h + (size_t)v * 128 + col);
    float4 o;
    o.x = sc * hv.x + acc.x * inv;
    o.y = sc * hv.y + acc.y * inv;
    o.z = sc * hv.z + acc.z * inv;
    o.w = sc * hv.w + acc.w * inv;
    *(float4*)(x + (size_t)v * 128 + col) = o;
}

// ---------------- GEMM: out[M,N] = act(A[M,128] @ Wm[N,128]^T + bias) ----------------
template <int N, bool RELU>
__global__ void __launch_bounds__(256) gemm_kernel(const float* __restrict__ A,
                                                   const float* __restrict__ Wm,
                                                   const float* __restrict__ bias,
                                                   float* __restrict__ out, int M) {
    constexpr int K = 128, BM = 128, KT = 32;
    constexpr int RN = N / 16;  // 8 or 4
    __shared__ float As[BM][KT + 1];
    __shared__ float Bs[KT][N + 1];

    int t = threadIdx.x;
    int tx = t & 15;
    int ty = t >> 4;
    int m0 = blockIdx.x * BM;

    float acc[8][RN];
#pragma unroll
    for (int i = 0; i < 8; ++i)
#pragma unroll
        for (int j = 0; j < RN; ++j) acc[i][j] = 0.f;

    for (int kc = 0; kc < K; kc += KT) {
        // load A tile [BM x KT], float4 per thread x4
#pragma unroll
        for (int i = 0; i < (BM * KT / 4) / 256; ++i) {  // 4 iters
            int f = t + i * 256;
            int row = f >> 3;
            int c4 = (f & 7) * 4;
            int gm = m0 + row;
            float4 v = make_float4(0.f, 0.f, 0.f, 0.f);
            if (gm < M) v = *(const float4*)(A + (size_t)gm * K + kc + c4);
            As[row][c4 + 0] = v.x;
            As[row][c4 + 1] = v.y;
            As[row][c4 + 2] = v.z;
            As[row][c4 + 3] = v.w;
        }
        // load B tile transposed: Bs[k][n] = Wm[n][kc+k]
#pragma unroll
        for (int i = 0; i < (KT * N / 4) / 256; ++i) {  // 4 (N=128) or 2 (N=64)
            int f = t + i * 256;
            int n = f >> 3;
            int kq = (f & 7) * 4;
            float4 v = *(const float4*)(Wm + (size_t)n * K + kc + kq);
            Bs[kq + 0][n] = v.x;
            Bs[kq + 1][n] = v.y;
            Bs[kq + 2][n] = v.z;
            Bs[kq + 3][n] = v.w;
        }
        __syncthreads();
#pragma unroll
        for (int k = 0; k < KT; ++k) {
            float a[8], bb[RN];
#pragma unroll
            for (int i = 0; i < 8; ++i) a[i] = As[ty * 8 + i][k];
#pragma unroll
            for (int j = 0; j < RN; ++j) bb[j] = Bs[k][j * 16 + tx];
#pragma unroll
            for (int i = 0; i < 8; ++i)
#pragma unroll
                for (int j = 0; j < RN; ++j) acc[i][j] += a[i] * bb[j];
        }
        __syncthreads();
    }

    float bj[RN];
#pragma unroll
    for (int j = 0; j < RN; ++j) bj[j] = bias[j * 16 + tx];
#pragma unroll
    for (int i = 0; i < 8; ++i) {
        int gm = m0 + ty * 8 + i;
        if (gm < M) {
#pragma unroll
            for (int j = 0; j < RN; ++j) {
                float v = acc[i][j] + bj[j];
                if (RELU) v = fmaxf(v, 0.f);
                out[(size_t)gm * N + j * 16 + tx] = v;
            }
        }
    }
}

// ---------------- launch ----------------
extern "C" void kernel_launch(void* const* d_in, const int* in_sizes, int n_in,
                              void* d_out, int out_size) {
    const float* inputs = (const float*)d_in[0];
    const float* fc_W   = (const float*)d_in[1];
    const float* fc_b   = (const float*)d_in[2];
    const float* W      = (const float*)d_in[3];
    const float* b      = (const float*)d_in[4];
    const float* W_last = (const float*)d_in[5];
    const float* b_last = (const float*)d_in[6];
    const float* eps    = (const float*)d_in[7];
    const int*   src    = (const int*)d_in[8];
    const int*   dst    = (const int*)d_in[9];
    float* out = (float*)d_out;

    float* hptr;
    float* xptr;
    cudaGetSymbolAddress((void**)&hptr, g_h);
    cudaGetSymbolAddress((void**)&xptr, g_x);

    // CSR build (deterministic structure; within-row order via atomics, fp-noise only)
    zero_deg_kernel<<<(NN + 255) / 256, 256>>>();
    hist_kernel<<<(NE + 255) / 256, 256>>>(dst);
    scan_kernel<<<1, 1024>>>();
    fill_kernel<<<(NE + 255) / 256, 256>>>(src, dst);

    const int gemm_grid = (NN + 127) / 128;  // 391
    const int agg_grid  = (NN + 7) / 8;      // 6250 blocks of 8 warps

    // input SLP
    gemm_kernel<128, true><<<gemm_grid, 256>>>(inputs, fc_W, fc_b, hptr, NN);

    // 3 hidden GIN layers
    for (int i = 0; i < 3; ++i) {
        aggregate_kernel<<<agg_grid, 256>>>(hptr, xptr, eps, i);
        gemm_kernel<128, true><<<gemm_grid, 256>>>(xptr, W + (size_t)i * 128 * 128,
                                                   b + (size_t)i * 128, hptr, NN);
    }

    // last GIN layer (no relu) straight into d_out
    aggregate_kernel<<<agg_grid, 256>>>(hptr, xptr, eps, 3);
    gemm_kernel<64, false><<<gemm_grid, 256>>>(xptr, W_last, b_last, out, NN);

    (void)in_sizes; (void)n_in; (void)out_size;
}

// round 3
// speedup vs baseline: 1.2618x; 1.2618x over previous
#include <cuda_runtime.h>
#include <cuda_bf16.h>
#include <cstdint>

#define NN 50000
#define NE 800000

// ---------------- device scratch (no allocs allowed) ----------------
__device__ __align__(16) float g_h[NN * 128];
__device__ __align__(16) __nv_bfloat16 g_xhi[NN * 128];
__device__ __align__(16) __nv_bfloat16 g_xlo[NN * 128];
__device__ __align__(16) __nv_bfloat16 g_whi[5 * 128 * 128];
__device__ __align__(16) __nv_bfloat16 g_wlo[5 * 128 * 128];
__device__ int   g_deg[NN];
__device__ float g_invdeg[NN];
__device__ int   g_rowptr[NN + 1];
__device__ int   g_cursor[NN];
__device__ int   g_esrc[NE];

// ---------------- helpers ----------------
__device__ __forceinline__ uint32_t smem_u32(const void* p) {
    uint32_t a;
    asm("{ .reg .u64 t; cvta.to.shared.u64 t, %1; cvt.u32.u64 %0, t; }" : "=r"(a) : "l"(p));
    return a;
}

__device__ __forceinline__ void ldsm4(uint32_t* r, uint32_t addr) {
    asm volatile("ldmatrix.sync.aligned.m8n8.x4.shared.b16 {%0,%1,%2,%3}, [%4];"
                 : "=r"(r[0]), "=r"(r[1]), "=r"(r[2]), "=r"(r[3]) : "r"(addr));
}

__device__ __forceinline__ void mma_bf16(float* c, const uint32_t* a, const uint32_t* b) {
    asm volatile(
        "mma.sync.aligned.m16n8k16.row.col.f32.bf16.bf16.f32 "
        "{%0,%1,%2,%3}, {%4,%5,%6,%7}, {%8,%9}, {%0,%1,%2,%3};"
        : "+f"(c[0]), "+f"(c[1]), "+f"(c[2]), "+f"(c[3])
        : "r"(a[0]), "r"(a[1]), "r"(a[2]), "r"(a[3]), "r"(b[0]), "r"(b[1]));
}

__device__ __forceinline__ void split_bf16(float v, __nv_bfloat16& hi, __nv_bfloat16& lo) {
    hi = __float2bfloat16_rn(v);
    lo = __float2bfloat16_rn(v - __bfloat162float(hi));
}
__device__ __forceinline__ uint32_t pack2(__nv_bfloat16 a, __nv_bfloat16 b) {
    __nv_bfloat162 t = __halves2bfloat162(a, b);
    return *reinterpret_cast<uint32_t*>(&t);
}

// ---------------- CSR build ----------------
__global__ void zero_deg_kernel() {
    int v = blockIdx.x * blockDim.x + threadIdx.x;
    if (v < NN) g_deg[v] = 0;
}

__global__ void hist_kernel(const int* __restrict__ dst) {
    int e = blockIdx.x * blockDim.x + threadIdx.x;
    if (e < NE) atomicAdd(&g_deg[dst[e]], 1);
}

__global__ void scan_kernel() {
    __shared__ int partial[1024];
    int t = threadIdx.x;
    const int C = (NN + 1023) / 1024;
    int beg = t * C;
    int end = min(beg + C, NN);
    int s = 0;
    for (int v = beg; v < end; ++v) s += g_deg[v];
    partial[t] = s;
    __syncthreads();
    for (int off = 1; off < 1024; off <<= 1) {
        int val = (t >= off) ? partial[t - off] : 0;
        __syncthreads();
        partial[t] += val;
        __syncthreads();
    }
    int run = (t == 0) ? 0 : partial[t - 1];
    for (int v = beg; v < end; ++v) {
        int d = g_deg[v];
        g_rowptr[v] = run;
        g_cursor[v] = 0;
        g_invdeg[v] = 1.0f / (float)(d > 0 ? d : 1);
        run += d;
    }
    if (t == 1023) g_rowptr[NN] = run;
}

__global__ void fill_kernel(const int* __restrict__ src, const int* __restrict__ dst) {
    int e = blockIdx.x * blockDim.x + threadIdx.x;
    if (e < NE) {
        int d = dst[e];
        int p = atomicAdd(&g_cursor[d], 1);
        g_esrc[g_rowptr[d] + p] = src[e];
    }
}

// ---------------- fp32 -> bf16 split convert ----------------
__global__ void convert_split_kernel(const float* __restrict__ in,
                                     __nv_bfloat16* __restrict__ ohi,
                                     __nv_bfloat16* __restrict__ olo, int n4) {
    int i = blockIdx.x * blockDim.x + threadIdx.x;
    if (i < n4) {
        float4 v = ((const float4*)in)[i];
        __nv_bfloat16 h0, l0, h1, l1, h2, l2, h3, l3;
        split_bf16(v.x, h0, l0);
        split_bf16(v.y, h1, l1);
        split_bf16(v.z, h2, l2);
        split_bf16(v.w, h3, l3);
        uint2 uh, ul;
        uh.x = pack2(h0, h1); uh.y = pack2(h2, h3);
        ul.x = pack2(l0, l1); ul.y = pack2(l2, l3);
        ((uint2*)ohi)[i] = uh;
        ((uint2*)olo)[i] = ul;
    }
}

// ---------------- aggregation: warp-per-node gather, writes bf16 split ----------------
__global__ void aggregate_kernel(const float* __restrict__ h,
                                 __nv_bfloat16* __restrict__ xhi,
                                 __nv_bfloat16* __restrict__ xlo,
                                 const float* __restrict__ eps, int li) {
    int warp = (blockIdx.x * blockDim.x + threadIdx.x) >> 5;
    if (warp >= NN) return;
    int lane = threadIdx.x & 31;
    int v = warp;
    int beg = g_rowptr[v], end = g_rowptr[v + 1];
    float4 acc = make_float4(0.f, 0.f, 0.f, 0.f);
    int e = beg;
    int col = lane * 4;
    for (; e + 4 <= end; e += 4) {
        int s0 = g_esrc[e + 0];
        int s1 = g_esrc[e + 1];
        int s2 = g_esrc[e + 2];
        int s3 = g_esrc[e + 3];
        float4 a = *(const float4*)(h + (size_t)s0 * 128 + col);
        float4 b = *(const float4*)(h + (size_t)s1 * 128 + col);
        float4 c = *(const float4*)(h + (size_t)s2 * 128 + col);
        float4 d = *(const float4*)(h + (size_t)s3 * 128 + col);
        acc.x += (a.x + b.x) + (c.x + d.x);
        acc.y += (a.y + b.y) + (c.y + d.y);
        acc.z += (a.z + b.z) + (c.z + d.z);
        acc.w += (a.w + b.w) + (c.w + d.w);
    }
    for (; e < end; ++e) {
        int s = g_esrc[e];
        float4 a = *(const float4*)(h + (size_t)s * 128 + col);
        acc.x += a.x; acc.y += a.y; acc.z += a.z; acc.w += a.w;
    }
    float inv = g_invdeg[v];
    float sc = 1.0f + eps[li];
    float4 hv = *(const float4*)(h + (size_t)v * 128 + col);
    float4 o;
    o.x = sc * hv.x + acc.x * inv;
    o.y = sc * hv.y + acc.y * inv;
    o.z = sc * hv.z + acc.z * inv;
    o.w = sc * hv.w + acc.w * inv;
    __nv_bfloat16 h0, l0, h1, l1, h2, l2, h3, l3;
    split_bf16(o.x, h0, l0);
    split_bf16(o.y, h1, l1);
    split_bf16(o.z, h2, l2);
    split_bf16(o.w, h3, l3);
    uint2 uh, ul;
    uh.x = pack2(h0, h1); uh.y = pack2(h2, h3);
    ul.x = pack2(l0, l1); ul.y = pack2(l2, l3);
    *(uint2*)&xhi[(size_t)v * 128 + col] = uh;
    *(uint2*)&xlo[(size_t)v * 128 + col] = ul;
}

// ---------------- tensor-core GEMM via mma.sync (bf16 split, fp32 accum) ----------------
// out[M,N] = act((Ahi+Alo)[M,128] @ (Bhi+Blo)[N,128]^T + bias)
template <int N, bool RELU>
__global__ void __launch_bounds__(256) gemm_mma(
    const __nv_bfloat16* __restrict__ Ahi, const __nv_bfloat16* __restrict__ Alo,
    const __nv_bfloat16* __restrict__ Bhi, const __nv_bfloat16* __restrict__ Blo,
    const float* __restrict__ bias, float* __restrict__ out, int M) {
    constexpr int LD = 136;           // bf16 elems per smem row (272B, 16B aligned)
    constexpr int NWN = N / 32;       // warps along N (4 or 2)
    constexpr int NWM = 8 / NWN;      // warps along M (2 or 4)
    constexpr int MW = 128 / NWM;     // rows per warp (64 or 32)
    constexpr int MT = MW / 16;       // m16 tiles per warp (4 or 2)

    extern __shared__ __nv_bfloat16 sm[];
    __nv_bfloat16* sAhi = sm;
    __nv_bfloat16* sAlo = sAhi + 128 * LD;
    __nv_bfloat16* sBhi = sAlo + 128 * LD;
    __nv_bfloat16* sBlo = sBhi + N * LD;
    __shared__ float s_bias[128];

    int tid = threadIdx.x;
    int m0 = blockIdx.x * 128;
    if (tid < N) s_bias[tid] = bias[tid];

    // stage A (128x128 bf16, both splits), 8 bf16 per uint4
    for (int i = tid; i < 2048; i += 256) {
        int row = i >> 4;
        int c8 = (i & 15) << 3;
        int gm = m0 + row;
        uint4 vh = make_uint4(0, 0, 0, 0), vl = make_uint4(0, 0, 0, 0);
        if (gm < M) {
            vh = *(const uint4*)(Ahi + (size_t)gm * 128 + c8);
            vl = *(const uint4*)(Alo + (size_t)gm * 128 + c8);
        }
        *(uint4*)&sAhi[row * LD + c8] = vh;
        *(uint4*)&sAlo[row * LD + c8] = vl;
    }
    // stage B (Nx128 bf16, both splits)
    for (int i = tid; i < N * 16; i += 256) {
        int row = i >> 4;
        int c8 = (i & 15) << 3;
        *(uint4*)&sBhi[row * LD + c8] = *(const uint4*)(Bhi + (size_t)row * 128 + c8);
        *(uint4*)&sBlo[row * LD + c8] = *(const uint4*)(Blo + (size_t)row * 128 + c8);
    }
    __syncthreads();

    int lane = tid & 31;
    int wid = tid >> 5;
    int wm = wid / NWN;
    int wn = wid % NWN;

    float acc[MT][4][4];
#pragma unroll
    for (int mt = 0; mt < MT; ++mt)
#pragma unroll
        for (int nt = 0; nt < 4; ++nt)
#pragma unroll
            for (int q = 0; q < 4; ++q) acc[mt][nt][q] = 0.f;

    const int ar = lane & 15;                 // A: row within 16
    const int ak = (lane >> 4) << 3;          // A: k offset 0/8
    const int br = (lane & 7) + ((lane >> 4) << 3);  // B: n row within 16
    const int bk = ((lane >> 3) & 1) << 3;    // B: k offset 0/8

#pragma unroll
    for (int ks = 0; ks < 8; ++ks) {
        int k0 = ks << 4;
        uint32_t ah[MT][4], al[MT][4];
#pragma unroll
        for (int mt = 0; mt < MT; ++mt) {
            int row = wm * MW + mt * 16 + ar;
            ldsm4(ah[mt], smem_u32(&sAhi[row * LD + k0 + ak]));
            ldsm4(al[mt], smem_u32(&sAlo[row * LD + k0 + ak]));
        }
        uint32_t bh[4][2], bl[4][2];
#pragma unroll
        for (int p = 0; p < 2; ++p) {
            int nrow = wn * 32 + p * 16 + br;
            uint32_t r[4];
            ldsm4(r, smem_u32(&sBhi[nrow * LD + k0 + bk]));
            bh[2 * p][0] = r[0]; bh[2 * p][1] = r[1];
            bh[2 * p + 1][0] = r[2]; bh[2 * p + 1][1] = r[3];
            ldsm4(r, smem_u32(&sBlo[nrow * LD + k0 + bk]));
            bl[2 * p][0] = r[0]; bl[2 * p][1] = r[1];
            bl[2 * p + 1][0] = r[2]; bl[2 * p + 1][1] = r[3];
        }
#pragma unroll
        for (int mt = 0; mt < MT; ++mt)
#pragma unroll
            for (int nt = 0; nt < 4; ++nt) {
                mma_bf16(acc[mt][nt], ah[mt], bh[nt]);
                mma_bf16(acc[mt][nt], ah[mt], bl[nt]);
                mma_bf16(acc[mt][nt], al[mt], bh[nt]);
            }
    }

    // epilogue: c0,c1 -> (row, col..col+1), c2,c3 -> (row+8, ...)
    int r = lane >> 2;
    int c2 = (lane & 3) << 1;
#pragma unroll
    for (int mt = 0; mt < MT; ++mt) {
        int gm = m0 + wm * MW + mt * 16 + r;
#pragma unroll
        for (int nt = 0; nt < 4; ++nt) {
            int col = wn * 32 + nt * 8 + c2;
            float b0 = s_bias[col], b1 = s_bias[col + 1];
            if (gm < M) {
                float2 v = make_float2(acc[mt][nt][0] + b0, acc[mt][nt][1] + b1);
                if (RELU) { v.x = fmaxf(v.x, 0.f); v.y = fmaxf(v.y, 0.f); }
                *(float2*)(out + (size_t)gm * N + col) = v;
            }
            if (gm + 8 < M) {
                float2 v = make_float2(acc[mt][nt][2] + b0, acc[mt][nt][3] + b1);
                if (RELU) { v.x = fmaxf(v.x, 0.f); v.y = fmaxf(v.y, 0.f); }
                *(float2*)(out + (size_t)(gm + 8) * N + col) = v;
            }
        }
    }
}

// ---------------- launch ----------------
extern "C" void kernel_launch(void* const* d_in, const int* in_sizes, int n_in,
                              void* d_out, int out_size) {
    const float* inputs = (const float*)d_in[0];
    const float* fc_W   = (const float*)d_in[1];
    const float* fc_b   = (const float*)d_in[2];
    const float* W      = (const float*)d_in[3];
    const float* b      = (const float*)d_in[4];
    const float* W_last = (const float*)d_in[5];
    const float* b_last = (const float*)d_in[6];
    const float* eps    = (const float*)d_in[7];
    const int*   src    = (const int*)d_in[8];
    const int*   dst    = (const int*)d_in[9];
    float* out = (float*)d_out;

    float* hptr;
    __nv_bfloat16 *xhi, *xlo, *whi, *wlo;
    cudaGetSymbolAddress((void**)&hptr, g_h);
    cudaGetSymbolAddress((void**)&xhi, g_xhi);
    cudaGetSymbolAddress((void**)&xlo, g_xlo);
    cudaGetSymbolAddress((void**)&whi, g_whi);
    cudaGetSymbolAddress((void**)&wlo, g_wlo);

    const int SMEM128 = (2 * 128 * 136 + 2 * 128 * 136) * 2;  // 139264 B
    const int SMEM64  = (2 * 128 * 136 + 2 * 64 * 136) * 2;   // 104448 B
    cudaFuncSetAttribute(gemm_mma<128, true>, cudaFuncAttributeMaxDynamicSharedMemorySize, SMEM128);
    cudaFuncSetAttribute(gemm_mma<64, false>, cudaFuncAttributeMaxDynamicSharedMemorySize, SMEM64);

    // CSR build
    zero_deg_kernel<<<(NN + 255) / 256, 256>>>();
    hist_kernel<<<(NE + 255) / 256, 256>>>(dst);
    scan_kernel<<<1, 1024>>>();
    fill_kernel<<<(NE + 255) / 256, 256>>>(src, dst);

    // weight + input bf16 splits
    convert_split_kernel<<<(16384 / 4 + 255) / 256, 256>>>(fc_W, whi, wlo, 16384 / 4);
    convert_split_kernel<<<(49152 / 4 + 255) / 256, 256>>>(W, whi + 16384, wlo + 16384, 49152 / 4);
    convert_split_kernel<<<(8192 / 4 + 255) / 256, 256>>>(W_last, whi + 4 * 16384, wlo + 4 * 16384, 8192 / 4);
    convert_split_kernel<<<(NN * 128 / 4 + 255) / 256, 256>>>(inputs, xhi, xlo, NN * 128 / 4);

    const int gemm_grid = (NN + 127) / 128;  // 391
    const int agg_grid  = (NN + 7) / 8;

    // input SLP
    gemm_mma<128, true><<<gemm_grid, 256, SMEM128>>>(xhi, xlo, whi, wlo, fc_b, hptr, NN);

    // 3 hidden GIN layers
    for (int i = 0; i < 3; ++i) {
        aggregate_kernel<<<agg_grid, 256>>>(hptr, xhi, xlo, eps, i);
        gemm_mma<128, true><<<gemm_grid, 256, SMEM128>>>(
            xhi, xlo, whi + (size_t)(1 + i) * 16384, wlo + (size_t)(1 + i) * 16384,
            b + (size_t)i * 128, hptr, NN);
    }

    // last GIN layer (no relu) straight into d_out
    aggregate_kernel<<<agg_grid, 256>>>(hptr, xhi, xlo, eps, 3);
    gemm_mma<64, false><<<gemm_grid, 256, SMEM64>>>(
        xhi, xlo, whi + (size_t)4 * 16384, wlo + (size_t)4 * 16384, b_last, out, NN);

    (void)in_sizes; (void)n_in; (void)out_size;
}